// round 3
// baseline (speedup 1.0000x reference)
#include <cuda_runtime.h>

// Problem constants (fixed instance)
#define B_ 8
#define C_ 96
#define H_ 224
#define W_ 224
#define BC_ (B_*C_)

// Scratch arena (single static device array; no cudaMalloc allowed).
// Aliasing: rec2 reuses ll2's slot (ll2 dead after fwd L2), rec1 reuses ll1's
// slot (ll1 dead after fwd L1). Offsets in floats:
#define OFF_COEFFS0 ((size_t)0)                               // BC*4*112*112
#define OFF_COEFFS1 (OFF_COEFFS0 + (size_t)BC_*4*112*112)     // BC*4*56*56
#define OFF_COEFFS2 (OFF_COEFFS1 + (size_t)BC_*4*56*56)       // BC*4*28*28
#define OFF_LL1     (OFF_COEFFS2 + (size_t)BC_*4*28*28)       // BC*112*112
#define OFF_LL2     (OFF_LL1     + (size_t)BC_*112*112)       // BC*56*56
#define OFF_REC2    OFF_LL2                                   // alias (ll2 dead)
#define OFF_REC1    OFF_LL1                                   // alias (ll1 dead)
#define ARENA_FLOATS (OFF_LL2 + (size_t)BC_*56*56)

__device__ float g_arena[ARENA_FLOATS];

// ---------------------------------------------------------------------------
// Forward level kernel: input (BC, hin, win) -> haar (on the fly) ->
// depthwise 5x5 conv per subband (SAME, zero pad in subband domain) * scale
// -> coeffs (BC,4,h,w); also writes raw (pre-conv) LL for next level.
// Tile: 32x32 outputs per block, 256 threads, 2x2 quad per thread.
// in_off: offset into g_arena, or use x pointer when use_x != 0.
// ---------------------------------------------------------------------------
__global__ __launch_bounds__(256) void fwd_kernel(
    const float* __restrict__ xin, int use_x, size_t in_off,
    int hin, int win,
    const float* __restrict__ wv,   // (4C,5,5) for this level
    const float* __restrict__ sv,   // (4C) for this level
    size_t coeffs_off,              // (BC,4,h,w)
    size_t ll_off, int has_ll)      // (BC,h,w)
{
    const int h = hin >> 1, w = win >> 1;
    const int bz = blockIdx.z;
    const int c  = bz % C_;
    const int oy0 = blockIdx.y * 32, ox0 = blockIdx.x * 32;

    __shared__ float sIn[72][73];
    __shared__ float sSub[4][36][37];
    __shared__ float sW[4][25];
    __shared__ float sScale[4];

    const int tid = threadIdx.x;

    // weights + scales to shared
    for (int i = tid; i < 100; i += 256) {
        int s = i / 25, k = i % 25;
        sW[s][k] = wv[(c * 4 + s) * 25 + k];
    }
    if (tid < 4) sScale[tid] = sv[c * 4 + tid];

    // load input tile with halo (subband halo 2 -> input halo 4)
    const int iy0 = 2 * oy0 - 4, ix0 = 2 * ox0 - 4;
    const float* inp = (use_x ? xin : (const float*)(g_arena + in_off))
                       + (size_t)bz * hin * win;
    for (int i = tid; i < 72 * 72; i += 256) {
        int r = i / 72, cc = i % 72;
        int gy = iy0 + r, gx = ix0 + cc;
        float v = 0.f;
        if (gy >= 0 && gy < hin && gx >= 0 && gx < win) v = inp[gy * win + gx];
        sIn[r][cc] = v;
    }
    __syncthreads();

    // haar into shared (36x36 subband region incl. halo)
    for (int i = tid; i < 36 * 36; i += 256) {
        int y = i / 36, x = i % 36;
        float a = sIn[2 * y][2 * x];
        float b = sIn[2 * y][2 * x + 1];
        float cc = sIn[2 * y + 1][2 * x];
        float d = sIn[2 * y + 1][2 * x + 1];
        sSub[0][y][x] = (a + b + cc + d) * 0.5f;
        sSub[1][y][x] = (a - b + cc - d) * 0.5f;
        sSub[2][y][x] = (a + b - cc - d) * 0.5f;
        sSub[3][y][x] = (a - b - cc + d) * 0.5f;
    }
    __syncthreads();

    const int ty = tid >> 4, tx = tid & 15;
    const int oy = oy0 + 2 * ty, ox = ox0 + 2 * tx;
    const bool wr = (oy < h) && (ox < w);   // h,w even -> quad all-in or all-out

    // write raw LL for next level (pre-conv)
    if (wr && has_ll) {
        float* lp = g_arena + ll_off + (size_t)bz * h * w;
        *(float2*)&lp[(size_t)oy * w + ox] =
            make_float2(sSub[0][2 * ty + 2][2 * tx + 2], sSub[0][2 * ty + 2][2 * tx + 3]);
        *(float2*)&lp[(size_t)(oy + 1) * w + ox] =
            make_float2(sSub[0][2 * ty + 3][2 * tx + 2], sSub[0][2 * ty + 3][2 * tx + 3]);
    }

    // depthwise conv per subband, 2x2 quad with register window
    #pragma unroll
    for (int s = 0; s < 4; s++) {
        float wreg[6][6];
        #pragma unroll
        for (int r = 0; r < 6; r++)
            #pragma unroll
            for (int q = 0; q < 6; q++)
                wreg[r][q] = sSub[s][2 * ty + r][2 * tx + q];
        float a00 = 0.f, a01 = 0.f, a10 = 0.f, a11 = 0.f;
        #pragma unroll
        for (int ky = 0; ky < 5; ky++)
            #pragma unroll
            for (int kx = 0; kx < 5; kx++) {
                float wt = sW[s][ky * 5 + kx];
                a00 = fmaf(wreg[ky][kx], wt, a00);
                a01 = fmaf(wreg[ky][kx + 1], wt, a01);
                a10 = fmaf(wreg[ky + 1][kx], wt, a10);
                a11 = fmaf(wreg[ky + 1][kx + 1], wt, a11);
            }
        if (wr) {
            float sc = sScale[s];
            float* cp = g_arena + coeffs_off + ((size_t)bz * 4 + s) * h * w;
            *(float2*)&cp[(size_t)oy * w + ox]       = make_float2(a00 * sc, a01 * sc);
            *(float2*)&cp[(size_t)(oy + 1) * w + ox] = make_float2(a10 * sc, a11 * sc);
        }
    }
}

// ---------------------------------------------------------------------------
// Inverse haar: out(BC,2h,2w) = ihaar( coeffs with LL += next_ll )
// One thread per coeff pixel; writes a 2x2 quad via two float2 stores.
// ---------------------------------------------------------------------------
__global__ __launch_bounds__(256) void inv_kernel(
    size_t coeffs_off, size_t nl_off, int has_nl,
    size_t out_off, int h, int w, int n)
{
    int idx = blockIdx.x * blockDim.x + threadIdx.x;
    if (idx >= n) return;
    int x = idx % w;
    int y = (idx / w) % h;
    int bz = idx / (w * h);
    size_t hw = (size_t)h * w;
    const float* cp = g_arena + coeffs_off + (size_t)bz * 4 * hw;
    size_t p = (size_t)y * w + x;
    float ll = cp[p];
    if (has_nl) ll += g_arena[nl_off + (size_t)bz * hw + p];
    float lh = cp[hw + p];
    float hl = cp[2 * hw + p];
    float hh = cp[3 * hw + p];
    float a = (ll + lh + hl + hh) * 0.5f;
    float b = (ll - lh + hl - hh) * 0.5f;
    float c = (ll + lh - hl - hh) * 0.5f;
    float d = (ll - lh - hl + hh) * 0.5f;
    int W2 = 2 * w;
    float* op = g_arena + out_off + (size_t)bz * 4 * hw;   // (2h)*(2w) = 4hw
    *(float2*)&op[(size_t)(2 * y) * W2 + 2 * x]     = make_float2(a, b);
    *(float2*)&op[(size_t)(2 * y + 1) * W2 + 2 * x] = make_float2(c, d);
}

// ---------------------------------------------------------------------------
// Final: out = dwconv(x, base_w)*base_scale + base_b + ihaar(coeffs0 + rec1)
// 32x32 tile per block, 256 threads, 2x2 quad per thread. A quad shares one
// coeff cell (output quads are even-aligned).
// ---------------------------------------------------------------------------
__global__ __launch_bounds__(256) void final_kernel(
    const float* __restrict__ x, const float* __restrict__ bw,
    const float* __restrict__ bb, const float* __restrict__ bs,
    size_t coeffs0_off, size_t rec1_off,
    float* __restrict__ out)
{
    const int bz = blockIdx.z;
    const int c  = bz % C_;
    const int oy0 = blockIdx.y * 32, ox0 = blockIdx.x * 32;

    __shared__ float sX[36][37];
    __shared__ float sC[4][16][17];
    __shared__ float sR[16][17];
    __shared__ float sW[25];

    const int tid = threadIdx.x;
    if (tid < 25) sW[tid] = bw[c * 25 + tid];

    const float* xp = x + (size_t)bz * H_ * W_;
    const int iy0 = oy0 - 2, ix0 = ox0 - 2;
    for (int i = tid; i < 36 * 36; i += 256) {
        int r = i / 36, cc = i % 36;
        int gy = iy0 + r, gx = ix0 + cc;
        sX[r][cc] = (gy >= 0 && gy < H_ && gx >= 0 && gx < W_) ? xp[gy * W_ + gx] : 0.f;
    }

    const int cy0 = oy0 >> 1, cx0 = ox0 >> 1;      // 112-domain, always in bounds
    const float* cp = g_arena + coeffs0_off + (size_t)bz * 4 * 112 * 112;
    const float* rp = g_arena + rec1_off + (size_t)bz * 112 * 112;
    for (int i = tid; i < 16 * 16; i += 256) {
        int r = i / 16, cc = i % 16;
        size_t p = (size_t)(cy0 + r) * 112 + (cx0 + cc);
        #pragma unroll
        for (int s = 0; s < 4; s++) sC[s][r][cc] = cp[(size_t)s * 112 * 112 + p];
        sR[r][cc] = rp[p];
    }
    __syncthreads();

    const int ty = tid >> 4, tx = tid & 15;
    const int oy = oy0 + 2 * ty, ox = ox0 + 2 * tx;   // 224 % 32 == 0: no bounds checks

    float wreg[6][6];
    #pragma unroll
    for (int r = 0; r < 6; r++)
        #pragma unroll
        for (int q = 0; q < 6; q++)
            wreg[r][q] = sX[2 * ty + r][2 * tx + q];

    float a00 = 0.f, a01 = 0.f, a10 = 0.f, a11 = 0.f;
    #pragma unroll
    for (int ky = 0; ky < 5; ky++)
        #pragma unroll
        for (int kx = 0; kx < 5; kx++) {
            float wt = sW[ky * 5 + kx];
            a00 = fmaf(wreg[ky][kx], wt, a00);
            a01 = fmaf(wreg[ky][kx + 1], wt, a01);
            a10 = fmaf(wreg[ky + 1][kx], wt, a10);
            a11 = fmaf(wreg[ky + 1][kx + 1], wt, a11);
        }

    float scale = bs[c], bias = bb[c];
    float ll = sC[0][ty][tx] + sR[ty][tx];
    float lh = sC[1][ty][tx];
    float hl = sC[2][ty][tx];
    float hh = sC[3][ty][tx];
    float ra = (ll + lh + hl + hh) * 0.5f;
    float rb = (ll - lh + hl - hh) * 0.5f;
    float rc = (ll + lh - hl - hh) * 0.5f;
    float rd = (ll - lh - hl + hh) * 0.5f;

    float* op = out + (size_t)bz * H_ * W_;
    *(float2*)&op[(size_t)oy * W_ + ox] =
        make_float2(fmaf(a00, scale, bias) + ra, fmaf(a01, scale, bias) + rb);
    *(float2*)&op[(size_t)(oy + 1) * W_ + ox] =
        make_float2(fmaf(a10, scale, bias) + rc, fmaf(a11, scale, bias) + rd);
}

// ---------------------------------------------------------------------------
extern "C" void kernel_launch(void* const* d_in, const int* in_sizes, int n_in,
                              void* d_out, int out_size)
{
    const float* x   = (const float*)d_in[0];   // (8,96,224,224)
    const float* bw  = (const float*)d_in[1];   // (96,1,5,5)
    const float* bb  = (const float*)d_in[2];   // (96)
    const float* bs  = (const float*)d_in[3];   // (1,96,1,1)
    const float* wv  = (const float*)d_in[4];   // (3,384,1,5,5)
    const float* sv  = (const float*)d_in[5];   // (3,1,384,1,1)
    float* out = (float*)d_out;

    const int LVL_W = 4 * C_ * 25;   // weight stride per level
    const int LVL_S = 4 * C_;        // scale stride per level

    // Forward levels
    fwd_kernel<<<dim3(4, 4, BC_), 256>>>(x, 1, 0, 224, 224,
                                         wv, sv, OFF_COEFFS0, OFF_LL1, 1);
    fwd_kernel<<<dim3(2, 2, BC_), 256>>>(nullptr, 0, OFF_LL1, 112, 112,
                                         wv + LVL_W, sv + LVL_S, OFF_COEFFS1, OFF_LL2, 1);
    fwd_kernel<<<dim3(1, 1, BC_), 256>>>(nullptr, 0, OFF_LL2, 56, 56,
                                         wv + 2 * LVL_W, sv + 2 * LVL_S, OFF_COEFFS2, 0, 0);

    // Inverse levels (rec2 aliases ll2 slot, rec1 aliases ll1 slot — both dead)
    {
        int n = BC_ * 28 * 28;
        inv_kernel<<<(n + 255) / 256, 256>>>(OFF_COEFFS2, 0, 0, OFF_REC2, 28, 28, n);
    }
    {
        int n = BC_ * 56 * 56;
        inv_kernel<<<(n + 255) / 256, 256>>>(OFF_COEFFS1, OFF_REC2, 1, OFF_REC1, 56, 56, n);
    }

    // Final fused: base dwconv + bias/scale + level-0 ihaar
    final_kernel<<<dim3(7, 7, BC_), 256>>>(x, bw, bb, bs, OFF_COEFFS0, OFF_REC1, out);
}